// round 2
// baseline (speedup 1.0000x reference)
#include <cuda_runtime.h>

#define NROWS 262144
#define HC 64
#define KOFF 27

// Intermediate (relu(conv1)) scratch: static device array (no allocations).
__device__ float g_mid[(size_t)NROWS * HC];

__device__ __forceinline__ unsigned long long pack2(float x, float y) {
    unsigned long long r;
    asm("mov.b64 %0, {%1, %2};" : "=l"(r) : "f"(x), "f"(y));
    return r;
}
__device__ __forceinline__ void unpack2(unsigned long long v, float& x, float& y) {
    asm("mov.b64 {%0, %1}, %2;" : "=f"(x), "=f"(y) : "l"(v));
}
// Blackwell packed dual-fp32 FMA (doubles fp32 throughput vs scalar FFMA).
__device__ __forceinline__ void ffma2(unsigned long long& d, unsigned long long a,
                                      unsigned long long b) {
    asm("fma.rn.f32x2 %0, %1, %2, %0;" : "+l"(d) : "l"(a), "l"(b));
}

// One sparse-conv layer over a 64-row tile.
//   out[r][o] = sum_k sum_c feats[nbr[r][k]][c] * W[k][c][o]   (+relu / +residual)
// Block: 128 threads. Thread tile: 4 rows x 8 cols. Tile: 64 rows x 64 cols.
template <bool RELU, bool RESID>
__global__ __launch_bounds__(128)
void spconv64(const float* __restrict__ feats,
              const float* __restrict__ Wmat,
              const int*   __restrict__ nbr,
              const float* __restrict__ resid,
              float*       __restrict__ out)
{
    __shared__ float As[64][68];   // gathered input tile, +4 pad (272B rows stay 16B-aligned)
    __shared__ float Bs[64][68];   // W[k]
    __shared__ int   idxs[64];

    const int tid  = threadIdx.x;
    const int row0 = blockIdx.x * 64;
    const int ty   = tid >> 3;     // 0..15  -> rows 4*ty..4*ty+3
    const int tx   = tid & 7;      // 0..7   -> cols 8*tx..8*tx+7
    const int gr   = tid >> 1;     // 0..63  gather row
    const int gs   = tid & 1;      // half-row segment (32 floats each)

    unsigned long long acc[4][4];  // [row][col-pair], each = 2 packed fp32
    #pragma unroll
    for (int i = 0; i < 4; i++)
        #pragma unroll
        for (int j = 0; j < 4; j++) acc[i][j] = 0ull;

    for (int k = 0; k < KOFF; k++) {
        __syncthreads();  // protect As/Bs/idxs from previous iteration's readers
        if (tid < 64) idxs[tid] = nbr[(size_t)(row0 + tid) * KOFF + k];
        __syncthreads();

        // Gather A tile: 2 threads per row, 8 float4 each.
        {
            const int idx = idxs[gr];
            if (idx < NROWS) {
                const float4* asrc =
                    reinterpret_cast<const float4*>(feats + (size_t)idx * HC + gs * 32);
                #pragma unroll
                for (int q = 0; q < 8; q++)
                    *reinterpret_cast<float4*>(&As[gr][gs * 32 + q * 4]) = asrc[q];
            } else {
                const float4 z = make_float4(0.f, 0.f, 0.f, 0.f);
                #pragma unroll
                for (int q = 0; q < 8; q++)
                    *reinterpret_cast<float4*>(&As[gr][gs * 32 + q * 4]) = z;
            }
            const float4* bsrc = reinterpret_cast<const float4*>(
                Wmat + (size_t)k * HC * HC + gr * HC + gs * 32);
            #pragma unroll
            for (int q = 0; q < 8; q++)
                *reinterpret_cast<float4*>(&Bs[gr][gs * 32 + q * 4]) = bsrc[q];
        }
        __syncthreads();

        // 64x64x64 GEMM accumulate, packed-f32x2 FMAs.
        #pragma unroll 2
        for (int kk = 0; kk < 64; kk += 4) {
            float4 av[4];
            #pragma unroll
            for (int i = 0; i < 4; i++)
                av[i] = *reinterpret_cast<const float4*>(&As[4 * ty + i][kk]);
            #pragma unroll
            for (int q = 0; q < 4; q++) {
                const float4 b0 = *reinterpret_cast<const float4*>(&Bs[kk + q][8 * tx]);
                const float4 b1 = *reinterpret_cast<const float4*>(&Bs[kk + q][8 * tx + 4]);
                unsigned long long bp[4];
                bp[0] = pack2(b0.x, b0.y);
                bp[1] = pack2(b0.z, b0.w);
                bp[2] = pack2(b1.x, b1.y);
                bp[3] = pack2(b1.z, b1.w);
                #pragma unroll
                for (int i = 0; i < 4; i++) {
                    const float a = (q == 0) ? av[i].x
                                  : (q == 1) ? av[i].y
                                  : (q == 2) ? av[i].z
                                             : av[i].w;
                    const unsigned long long ap = pack2(a, a);
                    #pragma unroll
                    for (int j = 0; j < 4; j++) ffma2(acc[i][j], ap, bp[j]);
                }
            }
        }
    }

    // Epilogue: relu (layer 1) or residual add (layer 2), vectorized stores.
    #pragma unroll
    for (int i = 0; i < 4; i++) {
        const int r = row0 + 4 * ty + i;
        float v[8];
        unpack2(acc[i][0], v[0], v[1]);
        unpack2(acc[i][1], v[2], v[3]);
        unpack2(acc[i][2], v[4], v[5]);
        unpack2(acc[i][3], v[6], v[7]);
        if (RELU) {
            #pragma unroll
            for (int j = 0; j < 8; j++) v[j] = fmaxf(v[j], 0.f);
        }
        if (RESID) {
            const float4 r0 =
                *reinterpret_cast<const float4*>(resid + (size_t)r * HC + 8 * tx);
            const float4 r1 =
                *reinterpret_cast<const float4*>(resid + (size_t)r * HC + 8 * tx + 4);
            v[0] += r0.x; v[1] += r0.y; v[2] += r0.z; v[3] += r0.w;
            v[4] += r1.x; v[5] += r1.y; v[6] += r1.z; v[7] += r1.w;
        }
        *reinterpret_cast<float4*>(out + (size_t)r * HC + 8 * tx) =
            make_float4(v[0], v[1], v[2], v[3]);
        *reinterpret_cast<float4*>(out + (size_t)r * HC + 8 * tx + 4) =
            make_float4(v[4], v[5], v[6], v[7]);
    }
}

extern "C" void kernel_launch(void* const* d_in, const int* in_sizes, int n_in,
                              void* d_out, int out_size) {
    const float* x   = (const float*)d_in[0];
    const float* Wa  = (const float*)d_in[1];
    const float* Wb  = (const float*)d_in[2];
    const int*   nbr = (const int*)d_in[3];
    float*       out = (float*)d_out;

    float* mid = nullptr;
    cudaGetSymbolAddress((void**)&mid, g_mid);

    const int nblocks = NROWS / 64;  // 4096
    spconv64<true,  false><<<nblocks, 128>>>(x,   Wa, nbr, nullptr, mid);
    spconv64<false, true ><<<nblocks, 128>>>(mid, Wb, nbr, x,       out);
}

// round 3
// speedup vs baseline: 1.0544x; 1.0544x over previous
#include <cuda_runtime.h>

#define NROWS 262144
#define HC 64
#define KOFF 27

// Intermediate (relu(conv1)) scratch: static device array (no allocations).
__device__ float g_mid[(size_t)NROWS * HC];

__device__ __forceinline__ unsigned long long pack2(float x, float y) {
    unsigned long long r;
    asm("mov.b64 %0, {%1, %2};" : "=l"(r) : "f"(x), "f"(y));
    return r;
}
__device__ __forceinline__ void unpack2(unsigned long long v, float& x, float& y) {
    asm("mov.b64 {%0, %1}, %2;" : "=f"(x), "=f"(y) : "l"(v));
}
// Blackwell packed dual-fp32 FMA (doubles fp32 throughput vs scalar FFMA).
__device__ __forceinline__ void ffma2(unsigned long long& d, unsigned long long a,
                                      unsigned long long b) {
    asm("fma.rn.f32x2 %0, %1, %2, %0;" : "+l"(d) : "l"(a), "l"(b));
}

// One sparse-conv layer over a 64-row tile.
//   out[r][o] = sum_k sum_c feats[nbr[r][k]][c] * W[k][c][o]   (+relu / +residual)
// Block: 128 threads. Thread tile: 4 rows x 8 cols. Tile: 64 rows x 64 cols.
template <bool RELU, bool RESID>
__global__ __launch_bounds__(128)
void spconv64(const float* __restrict__ feats,
              const float* __restrict__ Wmat,
              const int*   __restrict__ nbr,
              const float* __restrict__ resid,
              float*       __restrict__ out)
{
    __shared__ float As[64][68];   // gathered input tile, +4 pad (272B rows stay 16B-aligned)
    __shared__ float Bs[64][68];   // W[k]
    __shared__ int   idxs[64];

    const int tid  = threadIdx.x;
    const int row0 = blockIdx.x * 64;
    const int ty   = tid >> 3;     // 0..15  -> rows 4*ty..4*ty+3
    const int tx   = tid & 7;      // 0..7   -> cols 8*tx..8*tx+7
    const int gr   = tid >> 1;     // 0..63  gather row
    const int gs   = tid & 1;      // half-row segment (32 floats each)

    unsigned long long acc[4][4];  // [row][col-pair], each = 2 packed fp32
    #pragma unroll
    for (int i = 0; i < 4; i++)
        #pragma unroll
        for (int j = 0; j < 4; j++) acc[i][j] = 0ull;

    for (int k = 0; k < KOFF; k++) {
        __syncthreads();  // protect As/Bs/idxs from previous iteration's readers
        if (tid < 64) idxs[tid] = nbr[(size_t)(row0 + tid) * KOFF + k];
        __syncthreads();

        // Gather A tile: 2 threads per row, 8 float4 each.
        {
            const int idx = idxs[gr];
            if (idx < NROWS) {
                const float4* asrc =
                    reinterpret_cast<const float4*>(feats + (size_t)idx * HC + gs * 32);
                #pragma unroll
                for (int q = 0; q < 8; q++)
                    *reinterpret_cast<float4*>(&As[gr][gs * 32 + q * 4]) = asrc[q];
            } else {
                const float4 z = make_float4(0.f, 0.f, 0.f, 0.f);
                #pragma unroll
                for (int q = 0; q < 8; q++)
                    *reinterpret_cast<float4*>(&As[gr][gs * 32 + q * 4]) = z;
            }
            const float4* bsrc = reinterpret_cast<const float4*>(
                Wmat + (size_t)k * HC * HC + gr * HC + gs * 32);
            #pragma unroll
            for (int q = 0; q < 8; q++)
                *reinterpret_cast<float4*>(&Bs[gr][gs * 32 + q * 4]) = bsrc[q];
        }
        __syncthreads();

        // 64x64x64 GEMM accumulate, packed-f32x2 FMAs.
        #pragma unroll 2
        for (int kk = 0; kk < 64; kk += 4) {
            float4 av[4];
            #pragma unroll
            for (int i = 0; i < 4; i++)
                av[i] = *reinterpret_cast<const float4*>(&As[4 * ty + i][kk]);
            #pragma unroll
            for (int q = 0; q < 4; q++) {
                const float4 b0 = *reinterpret_cast<const float4*>(&Bs[kk + q][8 * tx]);
                const float4 b1 = *reinterpret_cast<const float4*>(&Bs[kk + q][8 * tx + 4]);
                unsigned long long bp[4];
                bp[0] = pack2(b0.x, b0.y);
                bp[1] = pack2(b0.z, b0.w);
                bp[2] = pack2(b1.x, b1.y);
                bp[3] = pack2(b1.z, b1.w);
                #pragma unroll
                for (int i = 0; i < 4; i++) {
                    const float a = (q == 0) ? av[i].x
                                  : (q == 1) ? av[i].y
                                  : (q == 2) ? av[i].z
                                             : av[i].w;
                    const unsigned long long ap = pack2(a, a);
                    #pragma unroll
                    for (int j = 0; j < 4; j++) ffma2(acc[i][j], ap, bp[j]);
                }
            }
        }
    }

    // Epilogue: relu (layer 1) or residual add (layer 2), vectorized stores.
    #pragma unroll
    for (int i = 0; i < 4; i++) {
        const int r = row0 + 4 * ty + i;
        float v[8];
        unpack2(acc[i][0], v[0], v[1]);
        unpack2(acc[i][1], v[2], v[3]);
        unpack2(acc[i][2], v[4], v[5]);
        unpack2(acc[i][3], v[6], v[7]);
        if (RELU) {
            #pragma unroll
            for (int j = 0; j < 8; j++) v[j] = fmaxf(v[j], 0.f);
        }
        if (RESID) {
            const float4 r0 =
                *reinterpret_cast<const float4*>(resid + (size_t)r * HC + 8 * tx);
            const float4 r1 =
                *reinterpret_cast<const float4*>(resid + (size_t)r * HC + 8 * tx + 4);
            v[0] += r0.x; v[1] += r0.y; v[2] += r0.z; v[3] += r0.w;
            v[4] += r1.x; v[5] += r1.y; v[6] += r1.z; v[7] += r1.w;
        }
        *reinterpret_cast<float4*>(out + (size_t)r * HC + 8 * tx) =
            make_float4(v[0], v[1], v[2], v[3]);
        *reinterpret_cast<float4*>(out + (size_t)r * HC + 8 * tx + 4) =
            make_float4(v[4], v[5], v[6], v[7]);
    }
}

extern "C" void kernel_launch(void* const* d_in, const int* in_sizes, int n_in,
                              void* d_out, int out_size) {
    const float* x   = (const float*)d_in[0];
    const float* Wa  = (const float*)d_in[1];
    const float* Wb  = (const float*)d_in[2];
    const int*   nbr = (const int*)d_in[3];
    float*       out = (float*)d_out;

    float* mid = nullptr;
    cudaGetSymbolAddress((void**)&mid, g_mid);

    const int nblocks = NROWS / 64;  // 4096
    spconv64<true,  false><<<nblocks, 128>>>(x,   Wa, nbr, nullptr, mid);
    spconv64<false, true ><<<nblocks, 128>>>(mid, Wb, nbr, x,       out);
}

// round 4
// speedup vs baseline: 1.0564x; 1.0019x over previous
#include <cuda_runtime.h>

#define NROWS 262144
#define HC 64
#define KOFF 27

// Intermediate (relu(conv1)) scratch: static device array (no allocations).
__device__ float g_mid[(size_t)NROWS * HC];

__device__ __forceinline__ unsigned long long pack2(float x, float y) {
    unsigned long long r;
    asm("mov.b64 %0, {%1, %2};" : "=l"(r) : "f"(x), "f"(y));
    return r;
}
__device__ __forceinline__ void unpack2(unsigned long long v, float& x, float& y) {
    asm("mov.b64 {%0, %1}, %2;" : "=f"(x), "=f"(y) : "l"(v));
}
// Blackwell packed dual-fp32 FMA (doubles fp32 throughput vs scalar FFMA).
__device__ __forceinline__ void ffma2(unsigned long long& d, unsigned long long a,
                                      unsigned long long b) {
    asm("fma.rn.f32x2 %0, %1, %2, %0;" : "+l"(d) : "l"(a), "l"(b));
}

// One sparse-conv layer over a 64-row tile.
//   out[r][o] = sum_k sum_c feats[nbr[r][k]][c] * W[k][c][o]   (+relu / +residual)
// Block: 128 threads. Thread tile: 4 rows x 8 cols. Tile: 64 rows x 64 cols.
template <bool RELU, bool RESID>
__global__ __launch_bounds__(128)
void spconv64(const float* __restrict__ feats,
              const float* __restrict__ Wmat,
              const int*   __restrict__ nbr,
              const float* __restrict__ resid,
              float*       __restrict__ out)
{
    __shared__ float As[64][68];   // gathered input tile, +4 pad (272B rows stay 16B-aligned)
    __shared__ float Bs[64][68];   // W[k]
    __shared__ int   idxs[64];

    const int tid  = threadIdx.x;
    const int row0 = blockIdx.x * 64;
    const int ty   = tid >> 3;     // 0..15  -> rows 4*ty..4*ty+3
    const int tx   = tid & 7;      // 0..7   -> cols 8*tx..8*tx+7
    const int gr   = tid >> 1;     // 0..63  gather row
    const int gs   = tid & 1;      // half-row segment (32 floats each)

    unsigned long long acc[4][4];  // [row][col-pair], each = 2 packed fp32
    #pragma unroll
    for (int i = 0; i < 4; i++)
        #pragma unroll
        for (int j = 0; j < 4; j++) acc[i][j] = 0ull;

    for (int k = 0; k < KOFF; k++) {
        __syncthreads();  // protect As/Bs/idxs from previous iteration's readers
        if (tid < 64) idxs[tid] = nbr[(size_t)(row0 + tid) * KOFF + k];
        __syncthreads();

        // Gather A tile: 2 threads per row, 8 float4 each.
        {
            const int idx = idxs[gr];
            if (idx < NROWS) {
                const float4* asrc =
                    reinterpret_cast<const float4*>(feats + (size_t)idx * HC + gs * 32);
                #pragma unroll
                for (int q = 0; q < 8; q++)
                    *reinterpret_cast<float4*>(&As[gr][gs * 32 + q * 4]) = asrc[q];
            } else {
                const float4 z = make_float4(0.f, 0.f, 0.f, 0.f);
                #pragma unroll
                for (int q = 0; q < 8; q++)
                    *reinterpret_cast<float4*>(&As[gr][gs * 32 + q * 4]) = z;
            }
            const float4* bsrc = reinterpret_cast<const float4*>(
                Wmat + (size_t)k * HC * HC + gr * HC + gs * 32);
            #pragma unroll
            for (int q = 0; q < 8; q++)
                *reinterpret_cast<float4*>(&Bs[gr][gs * 32 + q * 4]) = bsrc[q];
        }
        __syncthreads();

        // 64x64x64 GEMM accumulate, packed-f32x2 FMAs.
        #pragma unroll 2
        for (int kk = 0; kk < 64; kk += 4) {
            float4 av[4];
            #pragma unroll
            for (int i = 0; i < 4; i++)
                av[i] = *reinterpret_cast<const float4*>(&As[4 * ty + i][kk]);
            #pragma unroll
            for (int q = 0; q < 4; q++) {
                const float4 b0 = *reinterpret_cast<const float4*>(&Bs[kk + q][8 * tx]);
                const float4 b1 = *reinterpret_cast<const float4*>(&Bs[kk + q][8 * tx + 4]);
                unsigned long long bp[4];
                bp[0] = pack2(b0.x, b0.y);
                bp[1] = pack2(b0.z, b0.w);
                bp[2] = pack2(b1.x, b1.y);
                bp[3] = pack2(b1.z, b1.w);
                #pragma unroll
                for (int i = 0; i < 4; i++) {
                    const float a = (q == 0) ? av[i].x
                                  : (q == 1) ? av[i].y
                                  : (q == 2) ? av[i].z
                                             : av[i].w;
                    const unsigned long long ap = pack2(a, a);
                    #pragma unroll
                    for (int j = 0; j < 4; j++) ffma2(acc[i][j], ap, bp[j]);
                }
            }
        }
    }

    // Epilogue: relu (layer 1) or residual add (layer 2), vectorized stores.
    #pragma unroll
    for (int i = 0; i < 4; i++) {
        const int r = row0 + 4 * ty + i;
        float v[8];
        unpack2(acc[i][0], v[0], v[1]);
        unpack2(acc[i][1], v[2], v[3]);
        unpack2(acc[i][2], v[4], v[5]);
        unpack2(acc[i][3], v[6], v[7]);
        if (RELU) {
            #pragma unroll
            for (int j = 0; j < 8; j++) v[j] = fmaxf(v[j], 0.f);
        }
        if (RESID) {
            const float4 r0 =
                *reinterpret_cast<const float4*>(resid + (size_t)r * HC + 8 * tx);
            const float4 r1 =
                *reinterpret_cast<const float4*>(resid + (size_t)r * HC + 8 * tx + 4);
            v[0] += r0.x; v[1] += r0.y; v[2] += r0.z; v[3] += r0.w;
            v[4] += r1.x; v[5] += r1.y; v[6] += r1.z; v[7] += r1.w;
        }
        *reinterpret_cast<float4*>(out + (size_t)r * HC + 8 * tx) =
            make_float4(v[0], v[1], v[2], v[3]);
        *reinterpret_cast<float4*>(out + (size_t)r * HC + 8 * tx + 4) =
            make_float4(v[4], v[5], v[6], v[7]);
    }
}

extern "C" void kernel_launch(void* const* d_in, const int* in_sizes, int n_in,
                              void* d_out, int out_size) {
    const float* x   = (const float*)d_in[0];
    const float* Wa  = (const float*)d_in[1];
    const float* Wb  = (const float*)d_in[2];
    const int*   nbr = (const int*)d_in[3];
    float*       out = (float*)d_out;

    float* mid = nullptr;
    cudaGetSymbolAddress((void**)&mid, g_mid);

    const int nblocks = NROWS / 64;  // 4096
    spconv64<true,  false><<<nblocks, 128>>>(x,   Wa, nbr, nullptr, mid);
    spconv64<false, true ><<<nblocks, 128>>>(mid, Wb, nbr, x,       out);
}